// round 15
// baseline (speedup 1.0000x reference)
#include <cuda_runtime.h>
#include <cuda_bf16.h>
#include <cstdint>
#include <cstddef>

typedef __nv_bfloat16 bf16;

#define NSEQ 2048
#define TT   32
#define EE   256
#define HH   512
#define MROWS (NSEQ*TT)

#define BM 128
#define BN 64
#define BK 32
#define BKP 40
#define NT 256
#define NCTA_REC 128   // recurrence grid: (HH/BN=8) x (NSEQ/BM=16)

__device__ __align__(16) bf16  g_Ah[(size_t)MROWS * EE];
__device__ __align__(16) bf16  g_Al[(size_t)MROWS * EE];
__device__ __align__(16) float g_pre0[(size_t)TT * NSEQ * HH];
__device__ __align__(16) bf16  g_h0h[2][(size_t)NSEQ * HH];
__device__ __align__(16) bf16  g_h0l[2][(size_t)NSEQ * HH];
__device__ __align__(16) bf16  g_h1h[2][(size_t)NSEQ * HH];
__device__ __align__(16) bf16  g_h1l[2][(size_t)NSEQ * HH];
__device__ __align__(16) float g_h1f[(size_t)NSEQ * HH];

#define OFF_IH0 0
#define OFF_HH0 131072
#define OFF_IH1 393216
#define OFF_HH1 655360
#define WTOT    917504
__device__ __align__(16) bf16 g_Wh[WTOT];
__device__ __align__(16) bf16 g_Wl[WTOT];

// grid barrier state (monotonic generation; survives graph replays correctly)
__device__ unsigned g_bar_cnt;
__device__ unsigned g_bar_gen;

__device__ __forceinline__ void ldsm4(uint32_t* r, uint32_t a) {
    asm volatile("ldmatrix.sync.aligned.m8n8.x4.shared.b16 {%0,%1,%2,%3},[%4];"
                 : "=r"(r[0]), "=r"(r[1]), "=r"(r[2]), "=r"(r[3]) : "r"(a));
}
__device__ __forceinline__ void ldsm2(uint32_t* r, uint32_t a) {
    asm volatile("ldmatrix.sync.aligned.m8n8.x2.shared.b16 {%0,%1},[%2];"
                 : "=r"(r[0]), "=r"(r[1]) : "r"(a));
}
__device__ __forceinline__ void mma16816(float* c, const uint32_t* a, const uint32_t* b) {
    asm volatile(
        "mma.sync.aligned.m16n8k16.row.col.f32.bf16.bf16.f32 "
        "{%0,%1,%2,%3},{%4,%5,%6,%7},{%8,%9},{%0,%1,%2,%3};\n"
        : "+f"(c[0]), "+f"(c[1]), "+f"(c[2]), "+f"(c[3])
        : "r"(a[0]), "r"(a[1]), "r"(a[2]), "r"(a[3]), "r"(b[0]), "r"(b[1]));
}

struct SmemT {
    bf16 A[2][BM][BKP];
    bf16 B[2][BN][BKP];
};

// ACG=true: A-plane loads bypass L1 (h-state written by other SMs within the
// same persistent launch; L1 is not cross-SM coherent). B (weights) always
// cached in L1 — immutable after convert_weights, persists across steps.
template<bool ACG>
__device__ __forceinline__ uint4 ldA(const bf16* p) {
    if (ACG) return __ldcg(reinterpret_cast<const uint4*>(p));
    return *reinterpret_cast<const uint4*>(p);
}

template<bool ACG>
__device__ __forceinline__ void accumulate_pair(
    SmemT& sm,
    const bf16* __restrict__ Ah, const bf16* __restrict__ Al,
    const bf16* __restrict__ Bh, const bf16* __restrict__ Bl, int K,
    int m0, int n0, float (&acc)[2][4][4])
{
    const int tid  = threadIdx.x;
    const int lane = tid & 31;
    const int wid  = tid >> 5;
    const int wm   = wid & 3;
    const int wn   = wid >> 2;
    const int lrow = tid >> 2;
    const int lcol = (tid & 3) * 8;

    const int a_r = wm * 32 + (lane & 15);
    const int a_c = (lane >> 4) * 8;
    const int b_r = wn * 32 + (lane & 7);
    const int b_c = ((lane & 15) >> 3) * 8;

    const bf16* pA  = Ah + (size_t)(m0 + lrow) * K + lcol;
    const bf16* pAl = Al + (size_t)(m0 + lrow) * K + lcol;
    const bf16* pB  = Bh + (size_t)(n0 + lrow) * K + lcol;
    const bf16* pBl = Bl + (size_t)(n0 + lrow) * K + lcol;

    uint4 ra0 = ldA<ACG>(pA);
    uint4 ra1 = ldA<ACG>(pA + (size_t)64 * K);
    uint4 rl0 = ldA<ACG>(pAl);
    uint4 rl1 = ldA<ACG>(pAl + (size_t)64 * K);
    uint4 rb0 = *(const uint4*)pB;
    uint4 rb1 = *(const uint4*)pBl;

    for (int kc = 0; kc < K; kc += BK) {
        __syncthreads();
        *(uint4*)&sm.A[0][lrow][lcol]      = ra0;
        *(uint4*)&sm.A[0][lrow + 64][lcol] = ra1;
        *(uint4*)&sm.A[1][lrow][lcol]      = rl0;
        *(uint4*)&sm.A[1][lrow + 64][lcol] = rl1;
        *(uint4*)&sm.B[0][lrow][lcol]      = rb0;
        *(uint4*)&sm.B[1][lrow][lcol]      = rb1;
        if (kc + BK < K) {
            pA += BK; pAl += BK; pB += BK; pBl += BK;
            ra0 = ldA<ACG>(pA);
            ra1 = ldA<ACG>(pA + (size_t)64 * K);
            rl0 = ldA<ACG>(pAl);
            rl1 = ldA<ACG>(pAl + (size_t)64 * K);
            rb0 = *(const uint4*)pB;
            rb1 = *(const uint4*)pBl;
        }
        __syncthreads();
        #pragma unroll
        for (int s = 0; s < 2; s++) {
            uint32_t ah[2][4], alr[2][4], bh[4][2], bl[4][2];
            #pragma unroll
            for (int im = 0; im < 2; im++) {
                ldsm4(ah[im],  (uint32_t)__cvta_generic_to_shared(&sm.A[0][a_r + im*16][a_c + s*16]));
                ldsm4(alr[im], (uint32_t)__cvta_generic_to_shared(&sm.A[1][a_r + im*16][a_c + s*16]));
            }
            #pragma unroll
            for (int in = 0; in < 4; in++) {
                ldsm2(bh[in], (uint32_t)__cvta_generic_to_shared(&sm.B[0][b_r + in*8][b_c + s*16]));
                ldsm2(bl[in], (uint32_t)__cvta_generic_to_shared(&sm.B[1][b_r + in*8][b_c + s*16]));
            }
            #pragma unroll
            for (int im = 0; im < 2; im++)
                #pragma unroll
                for (int in = 0; in < 4; in++) {
                    mma16816(acc[im][in], ah[im],  bh[in]);
                    mma16816(acc[im][in], ah[im],  bl[in]);
                    mma16816(acc[im][in], alr[im], bh[in]);
                }
        }
    }
}

// ---------------- pre-projection GEMM (single launch; unchanged math) ----------------
__global__ __launch_bounds__(NT) void gemm3p(
    const bf16* A1h, const bf16* A1l, const bf16* B1h, const bf16* B1l, int K1,
    const float* __restrict__ bias_a, const float* __restrict__ bias_b,
    float* __restrict__ Of)
{
    __shared__ SmemT sm;
    float acc[2][4][4];
    #pragma unroll
    for (int i = 0; i < 2; i++)
        #pragma unroll
        for (int j = 0; j < 4; j++)
            #pragma unroll
            for (int k = 0; k < 4; k++) acc[i][j][k] = 0.f;

    const int m0 = blockIdx.y * BM;
    const int n0 = blockIdx.x * BN;

    accumulate_pair<false>(sm, A1h, A1l, B1h, B1l, K1, m0, n0, acc);

    const int tid = threadIdx.x, lane = tid & 31, wid = tid >> 5;
    const int wm = wid & 3, wn = wid >> 2;

    #pragma unroll
    for (int im = 0; im < 2; im++)
        #pragma unroll
        for (int in = 0; in < 4; in++) {
            int r0 = m0 + wm * 32 + im * 16 + (lane >> 2);
            int c0 = n0 + wn * 32 + in * 8 + (lane & 3) * 2;
            float t0 = bias_a[c0] + bias_b[c0];
            float t1 = bias_a[c0 + 1] + bias_b[c0 + 1];
            float v0 = acc[im][in][0] + t0, v1 = acc[im][in][1] + t1;
            float v2 = acc[im][in][2] + t0, v3 = acc[im][in][3] + t1;
            // scatter row r = n*T + t  ->  [t][n][h]
            int t  = r0 & (TT - 1), n = r0 >> 5;
            *(float2*)&Of[((size_t)t * NSEQ + n) * HH + c0] = make_float2(v0, v1);
            int t2 = (r0 + 8) & (TT - 1), n2 = (r0 + 8) >> 5;
            *(float2*)&Of[((size_t)t2 * NSEQ + n2) * HH + c0] = make_float2(v2, v3);
        }
}

// ---------------- persistent recurrence kernel ----------------
__device__ __forceinline__ void grid_sync_rec() {
    __syncthreads();
    if (threadIdx.x == 0) {
        __threadfence();
        unsigned gen = *(volatile unsigned*)&g_bar_gen;   // read BEFORE arriving
        unsigned t = atomicAdd(&g_bar_cnt, 1u);
        if (t == NCTA_REC - 1u) {
            g_bar_cnt = 0u;
            __threadfence();
            *(volatile unsigned*)&g_bar_gen = gen + 1u;
        } else {
            while (*(volatile unsigned*)&g_bar_gen == gen) { __nanosleep(64); }
        }
        __threadfence();
    }
    __syncthreads();
}

__global__ __launch_bounds__(NT) void recurrence_persistent(
    const bf16* __restrict__ Wh, const bf16* __restrict__ Wl,
    const float* __restrict__ pre0,
    const float* __restrict__ b_ih1, const float* __restrict__ b_hh1,
    bf16* __restrict__ h0h, bf16* __restrict__ h0l,
    bf16* __restrict__ h1h, bf16* __restrict__ h1l,
    float* __restrict__ h1f)
{
    __shared__ SmemT sm;
    const size_t PL = (size_t)NSEQ * HH;   // plane (ping-pong) stride
    const int m0 = blockIdx.y * BM;
    const int n0 = blockIdx.x * BN;
    const int tid = threadIdx.x, lane = tid & 31, wid = tid >> 5;
    const int wm = wid & 3, wn = wid >> 2;

    for (int t = 0; t < TT; t++) {
        const int rd = t & 1, wr = rd ^ 1;

        // ---- layer 0: h0_t = relu(pre0[t] + h0_{t-1} @ W_hh0^T) ----
        float acc[2][4][4];
        #pragma unroll
        for (int i = 0; i < 2; i++)
            #pragma unroll
            for (int j = 0; j < 4; j++)
                #pragma unroll
                for (int k = 0; k < 4; k++) acc[i][j][k] = 0.f;

        if (t > 0)
            accumulate_pair<true>(sm, h0h + rd * PL, h0l + rd * PL,
                                  Wh + OFF_HH0, Wl + OFF_HH0, HH, m0, n0, acc);

        const float* p0t = pre0 + (size_t)t * PL;
        #pragma unroll
        for (int im = 0; im < 2; im++)
            #pragma unroll
            for (int in = 0; in < 4; in++) {
                int r0 = m0 + wm * 32 + im * 16 + (lane >> 2);
                int c0 = n0 + wn * 32 + in * 8 + (lane & 3) * 2;
                float2 q0 = *(const float2*)&p0t[(size_t)r0 * HH + c0];
                float2 q1 = *(const float2*)&p0t[(size_t)(r0 + 8) * HH + c0];
                float v0 = fmaxf(acc[im][in][0] + q0.x, 0.f);
                float v1 = fmaxf(acc[im][in][1] + q0.y, 0.f);
                float v2 = fmaxf(acc[im][in][2] + q1.x, 0.f);
                float v3 = fmaxf(acc[im][in][3] + q1.y, 0.f);
                bf16 a0 = __float2bfloat16(v0), a1 = __float2bfloat16(v1);
                bf16 a2 = __float2bfloat16(v2), a3 = __float2bfloat16(v3);
                __nv_bfloat162 p;
                p.x = a0; p.y = a1; *(__nv_bfloat162*)&h0h[wr * PL + (size_t)r0 * HH + c0] = p;
                p.x = a2; p.y = a3; *(__nv_bfloat162*)&h0h[wr * PL + (size_t)(r0 + 8) * HH + c0] = p;
                bf16 l0 = __float2bfloat16(v0 - __bfloat162float(a0));
                bf16 l1 = __float2bfloat16(v1 - __bfloat162float(a1));
                bf16 l2 = __float2bfloat16(v2 - __bfloat162float(a2));
                bf16 l3 = __float2bfloat16(v3 - __bfloat162float(a3));
                p.x = l0; p.y = l1; *(__nv_bfloat162*)&h0l[wr * PL + (size_t)r0 * HH + c0] = p;
                p.x = l2; p.y = l3; *(__nv_bfloat162*)&h0l[wr * PL + (size_t)(r0 + 8) * HH + c0] = p;
            }

        grid_sync_rec();

        // ---- layer 1: h1_t = relu(h0_t @ W_ih1^T + h1_{t-1} @ W_hh1^T + b) ----
        #pragma unroll
        for (int i = 0; i < 2; i++)
            #pragma unroll
            for (int j = 0; j < 4; j++)
                #pragma unroll
                for (int k = 0; k < 4; k++) acc[i][j][k] = 0.f;

        accumulate_pair<true>(sm, h0h + wr * PL, h0l + wr * PL,
                              Wh + OFF_IH1, Wl + OFF_IH1, HH, m0, n0, acc);
        if (t > 0)
            accumulate_pair<true>(sm, h1h + rd * PL, h1l + rd * PL,
                                  Wh + OFF_HH1, Wl + OFF_HH1, HH, m0, n0, acc);

        #pragma unroll
        for (int im = 0; im < 2; im++)
            #pragma unroll
            for (int in = 0; in < 4; in++) {
                int r0 = m0 + wm * 32 + im * 16 + (lane >> 2);
                int c0 = n0 + wn * 32 + in * 8 + (lane & 3) * 2;
                float t0 = b_ih1[c0] + b_hh1[c0];
                float t1 = b_ih1[c0 + 1] + b_hh1[c0 + 1];
                float v0 = fmaxf(acc[im][in][0] + t0, 0.f);
                float v1 = fmaxf(acc[im][in][1] + t1, 0.f);
                float v2 = fmaxf(acc[im][in][2] + t0, 0.f);
                float v3 = fmaxf(acc[im][in][3] + t1, 0.f);
                bf16 a0 = __float2bfloat16(v0), a1 = __float2bfloat16(v1);
                bf16 a2 = __float2bfloat16(v2), a3 = __float2bfloat16(v3);
                __nv_bfloat162 p;
                p.x = a0; p.y = a1; *(__nv_bfloat162*)&h1h[wr * PL + (size_t)r0 * HH + c0] = p;
                p.x = a2; p.y = a3; *(__nv_bfloat162*)&h1h[wr * PL + (size_t)(r0 + 8) * HH + c0] = p;
                bf16 l0 = __float2bfloat16(v0 - __bfloat162float(a0));
                bf16 l1 = __float2bfloat16(v1 - __bfloat162float(a1));
                bf16 l2 = __float2bfloat16(v2 - __bfloat162float(a2));
                bf16 l3 = __float2bfloat16(v3 - __bfloat162float(a3));
                p.x = l0; p.y = l1; *(__nv_bfloat162*)&h1l[wr * PL + (size_t)r0 * HH + c0] = p;
                p.x = l2; p.y = l3; *(__nv_bfloat162*)&h1l[wr * PL + (size_t)(r0 + 8) * HH + c0] = p;
                if (t == TT - 1) {
                    *(float2*)&h1f[(size_t)r0 * HH + c0] = make_float2(v0, v1);
                    *(float2*)&h1f[(size_t)(r0 + 8) * HH + c0] = make_float2(v2, v3);
                }
            }

        grid_sync_rec();
    }
}

__global__ void embed_kernel(const int* __restrict__ x, const float* __restrict__ embed) {
    size_t i = (size_t)blockIdx.x * blockDim.x + threadIdx.x;
    size_t r  = i >> 6;
    int    e4 = (int)(i & 63) << 2;
    int tok = x[r];
    float4 v = *(const float4*)(embed + (size_t)tok * EE + e4);
    size_t off = r * EE + e4;
    float vv[4] = {v.x, v.y, v.z, v.w};
    #pragma unroll
    for (int j = 0; j < 4; j++) {
        bf16 h = __float2bfloat16(vv[j]);
        g_Ah[off + j] = h;
        g_Al[off + j] = __float2bfloat16(vv[j] - __bfloat162float(h));
    }
}

__global__ void convert_weights(const float* __restrict__ w0, const float* __restrict__ w1,
                                const float* __restrict__ w2, const float* __restrict__ w3) {
    int i = blockIdx.x * 256 + threadIdx.x;
    if (i >= WTOT) return;
    float v;
    if      (i < OFF_HH0) v = w0[i - OFF_IH0];
    else if (i < OFF_IH1) v = w1[i - OFF_HH0];
    else if (i < OFF_HH1) v = w2[i - OFF_IH1];
    else                  v = w3[i - OFF_HH1];
    bf16 h = __float2bfloat16(v);
    g_Wh[i] = h;
    g_Wl[i] = __float2bfloat16(v - __bfloat162float(h));
}

__global__ void final_kernel(const float* __restrict__ h1, const float* __restrict__ Wp,
                             const float* __restrict__ bp, float* __restrict__ out) {
    __shared__ float wc[1024];
    __shared__ float red[256];
    __shared__ float ctermS;
    int b = blockIdx.x, tid = threadIdx.x;
    const float* Hb = h1 + (size_t)b * 256 * HH;
    float s0 = 0.f, s1 = 0.f;
    for (int cell = 0; cell < 256; cell++) {
        const float* row = Hb + (size_t)cell * HH;
        s0 += row[tid];
        s1 += row[tid + 256];
    }
    wc[tid]       = Wp[tid]       - Wp[HH + tid];
    wc[tid + 256] = Wp[tid + 256] - Wp[HH + tid + 256];
    red[tid] = s0 * Wp[HH + tid] + s1 * Wp[HH + tid + 256];
    __syncthreads();
    for (int s = 128; s > 0; s >>= 1) {
        if (tid < s) red[tid] += red[tid + s];
        __syncthreads();
    }
    if (tid == 0) ctermS = red[0] + bp[0];
    __syncthreads();
    int warp = tid >> 5, lane = tid & 31;
    for (int cell = warp; cell < 256; cell += 8) {
        const float* row = Hb + (size_t)cell * HH;
        float a = 0.f;
        for (int c = lane; c < HH; c += 32) a += row[c] * wc[c];
        #pragma unroll
        for (int o = 16; o; o >>= 1) a += __shfl_xor_sync(0xffffffffu, a, o);
        if (lane == 0) out[(size_t)b * 256 + cell] = a + ctermS;
    }
}

extern "C" void kernel_launch(void* const* d_in, const int* in_sizes, int n_in,
                              void* d_out, int out_size) {
    (void)in_sizes; (void)n_in; (void)out_size;
    const int*   x      = (const int*)  d_in[0];
    const float* embedp = (const float*)d_in[1];
    const float* W_ih0  = (const float*)d_in[2];
    const float* W_hh0  = (const float*)d_in[3];
    const float* b_ih0  = (const float*)d_in[4];
    const float* b_hh0  = (const float*)d_in[5];
    const float* W_ih1  = (const float*)d_in[6];
    const float* W_hh1  = (const float*)d_in[7];
    const float* b_ih1  = (const float*)d_in[8];
    const float* b_hh1  = (const float*)d_in[9];
    const float* W_pred = (const float*)d_in[10];
    const float* b_pred = (const float*)d_in[11];
    float* out = (float*)d_out;

    bf16 *Ah, *Al, *Wh, *Wl, *h0h, *h0l, *h1h, *h1l;
    float *pre0, *h1f;
    cudaGetSymbolAddress((void**)&Ah,  g_Ah);
    cudaGetSymbolAddress((void**)&Al,  g_Al);
    cudaGetSymbolAddress((void**)&Wh,  g_Wh);
    cudaGetSymbolAddress((void**)&Wl,  g_Wl);
    cudaGetSymbolAddress((void**)&h0h, g_h0h);
    cudaGetSymbolAddress((void**)&h0l, g_h0l);
    cudaGetSymbolAddress((void**)&h1h, g_h1h);
    cudaGetSymbolAddress((void**)&h1l, g_h1l);
    cudaGetSymbolAddress((void**)&pre0, g_pre0);
    cudaGetSymbolAddress((void**)&h1f,  g_h1f);

    convert_weights<<<(WTOT + 255) / 256, 256>>>(W_ih0, W_hh0, W_ih1, W_hh1);
    embed_kernel<<<(MROWS * EE / 4 + 255) / 256, 256>>>(x, embedp);

    // pre0 = emb @ W_ih0^T + b_ih0 + b_hh0, scattered to [t][n][h]
    gemm3p<<<dim3(HH / BN, MROWS / BM), NT>>>(
        Ah, Al, Wh + OFF_IH0, Wl + OFF_IH0, EE, b_ih0, b_hh0, pre0);

    // entire 32-step, 2-layer recurrence in ONE persistent kernel
    recurrence_persistent<<<dim3(HH / BN, NSEQ / BM), NT>>>(
        Wh, Wl, pre0, b_ih1, b_hh1, h0h, h0l, h1h, h1l, h1f);

    final_kernel<<<8, 256>>>(h1f, W_pred, b_pred, out);
}

// round 17
// speedup vs baseline: 1.3269x; 1.3269x over previous
#include <cuda_runtime.h>
#include <cuda_bf16.h>
#include <cstdint>
#include <cstddef>

typedef __nv_bfloat16 bf16;

#define NSEQ 2048
#define TT   32
#define EE   256
#define HH   512
#define MROWS (NSEQ*TT)

#define BM 128
#define BN 64
// old 8-warp path (pre-projection GEMM)
#define BK 32
#define BKP 40
#define NT 256
// new 16-warp recurrence path
#define BK2 64
#define BKP2 72
#define NT2 512
#define NCTA_REC 128

__device__ __align__(16) bf16  g_Ah[(size_t)MROWS * EE];
__device__ __align__(16) bf16  g_Al[(size_t)MROWS * EE];
__device__ __align__(16) float g_pre0[(size_t)TT * NSEQ * HH];
__device__ __align__(16) bf16  g_h0h[2][(size_t)NSEQ * HH];
__device__ __align__(16) bf16  g_h0l[2][(size_t)NSEQ * HH];
__device__ __align__(16) bf16  g_h1h[2][(size_t)NSEQ * HH];
__device__ __align__(16) bf16  g_h1l[2][(size_t)NSEQ * HH];
__device__ __align__(16) float g_h1f[(size_t)NSEQ * HH];

#define OFF_IH0 0
#define OFF_HH0 131072
#define OFF_IH1 393216
#define OFF_HH1 655360
#define WTOT    917504
__device__ __align__(16) bf16 g_Wh[WTOT];
__device__ __align__(16) bf16 g_Wl[WTOT];

__device__ unsigned g_bar_cnt;
__device__ unsigned g_bar_gen;

__device__ __forceinline__ void ldsm4(uint32_t* r, uint32_t a) {
    asm volatile("ldmatrix.sync.aligned.m8n8.x4.shared.b16 {%0,%1,%2,%3},[%4];"
                 : "=r"(r[0]), "=r"(r[1]), "=r"(r[2]), "=r"(r[3]) : "r"(a));
}
__device__ __forceinline__ void ldsm2(uint32_t* r, uint32_t a) {
    asm volatile("ldmatrix.sync.aligned.m8n8.x2.shared.b16 {%0,%1},[%2];"
                 : "=r"(r[0]), "=r"(r[1]) : "r"(a));
}
__device__ __forceinline__ void mma16816(float* c, const uint32_t* a, const uint32_t* b) {
    asm volatile(
        "mma.sync.aligned.m16n8k16.row.col.f32.bf16.bf16.f32 "
        "{%0,%1,%2,%3},{%4,%5,%6,%7},{%8,%9},{%0,%1,%2,%3};\n"
        : "+f"(c[0]), "+f"(c[1]), "+f"(c[2]), "+f"(c[3])
        : "r"(a[0]), "r"(a[1]), "r"(a[2]), "r"(a[3]), "r"(b[0]), "r"(b[1]));
}

template<bool ACG>
__device__ __forceinline__ uint4 ldA(const bf16* p) {
    if (ACG) return __ldcg(reinterpret_cast<const uint4*>(p));
    return *reinterpret_cast<const uint4*>(p);
}

// ================= old 8-warp GEMM (pre-projection only) =================
struct SmemT {
    bf16 A[2][BM][BKP];
    bf16 B[2][BN][BKP];
};

__device__ __forceinline__ void accumulate_pair8(
    SmemT& sm,
    const bf16* __restrict__ Ah, const bf16* __restrict__ Al,
    const bf16* __restrict__ Bh, const bf16* __restrict__ Bl, int K,
    int m0, int n0, float (&acc)[2][4][4])
{
    const int tid  = threadIdx.x;
    const int lane = tid & 31;
    const int wid  = tid >> 5;
    const int wm   = wid & 3;
    const int wn   = wid >> 2;
    const int lrow = tid >> 2;
    const int lcol = (tid & 3) * 8;

    const int a_r = wm * 32 + (lane & 15);
    const int a_c = (lane >> 4) * 8;
    const int b_r = wn * 32 + (lane & 7);
    const int b_c = ((lane & 15) >> 3) * 8;

    const bf16* pA  = Ah + (size_t)(m0 + lrow) * K + lcol;
    const bf16* pAl = Al + (size_t)(m0 + lrow) * K + lcol;
    const bf16* pB  = Bh + (size_t)(n0 + lrow) * K + lcol;
    const bf16* pBl = Bl + (size_t)(n0 + lrow) * K + lcol;

    uint4 ra0 = ldA<false>(pA);
    uint4 ra1 = ldA<false>(pA + (size_t)64 * K);
    uint4 rl0 = ldA<false>(pAl);
    uint4 rl1 = ldA<false>(pAl + (size_t)64 * K);
    uint4 rb0 = *(const uint4*)pB;
    uint4 rb1 = *(const uint4*)pBl;

    for (int kc = 0; kc < K; kc += BK) {
        __syncthreads();
        *(uint4*)&sm.A[0][lrow][lcol]      = ra0;
        *(uint4*)&sm.A[0][lrow + 64][lcol] = ra1;
        *(uint4*)&sm.A[1][lrow][lcol]      = rl0;
        *(uint4*)&sm.A[1][lrow + 64][lcol] = rl1;
        *(uint4*)&sm.B[0][lrow][lcol]      = rb0;
        *(uint4*)&sm.B[1][lrow][lcol]      = rb1;
        if (kc + BK < K) {
            pA += BK; pAl += BK; pB += BK; pBl += BK;
            ra0 = ldA<false>(pA);
            ra1 = ldA<false>(pA + (size_t)64 * K);
            rl0 = ldA<false>(pAl);
            rl1 = ldA<false>(pAl + (size_t)64 * K);
            rb0 = *(const uint4*)pB;
            rb1 = *(const uint4*)pBl;
        }
        __syncthreads();
        #pragma unroll
        for (int s = 0; s < 2; s++) {
            uint32_t ah[2][4], alr[2][4], bh[4][2], bl[4][2];
            #pragma unroll
            for (int im = 0; im < 2; im++) {
                ldsm4(ah[im],  (uint32_t)__cvta_generic_to_shared(&sm.A[0][a_r + im*16][a_c + s*16]));
                ldsm4(alr[im], (uint32_t)__cvta_generic_to_shared(&sm.A[1][a_r + im*16][a_c + s*16]));
            }
            #pragma unroll
            for (int in = 0; in < 4; in++) {
                ldsm2(bh[in], (uint32_t)__cvta_generic_to_shared(&sm.B[0][b_r + in*8][b_c + s*16]));
                ldsm2(bl[in], (uint32_t)__cvta_generic_to_shared(&sm.B[1][b_r + in*8][b_c + s*16]));
            }
            #pragma unroll
            for (int im = 0; im < 2; im++)
                #pragma unroll
                for (int in = 0; in < 4; in++) {
                    mma16816(acc[im][in], ah[im],  bh[in]);
                    mma16816(acc[im][in], ah[im],  bl[in]);
                    mma16816(acc[im][in], alr[im], bh[in]);
                }
        }
    }
}

__global__ __launch_bounds__(NT) void gemm3p(
    const bf16* A1h, const bf16* A1l, const bf16* B1h, const bf16* B1l, int K1,
    const float* __restrict__ bias_a, const float* __restrict__ bias_b,
    float* __restrict__ Of)
{
    __shared__ SmemT sm;
    float acc[2][4][4];
    #pragma unroll
    for (int i = 0; i < 2; i++)
        #pragma unroll
        for (int j = 0; j < 4; j++)
            #pragma unroll
            for (int k = 0; k < 4; k++) acc[i][j][k] = 0.f;

    const int m0 = blockIdx.y * BM;
    const int n0 = blockIdx.x * BN;

    accumulate_pair8(sm, A1h, A1l, B1h, B1l, K1, m0, n0, acc);

    const int tid = threadIdx.x, lane = tid & 31, wid = tid >> 5;
    const int wm = wid & 3, wn = wid >> 2;

    #pragma unroll
    for (int im = 0; im < 2; im++)
        #pragma unroll
        for (int in = 0; in < 4; in++) {
            int r0 = m0 + wm * 32 + im * 16 + (lane >> 2);
            int c0 = n0 + wn * 32 + in * 8 + (lane & 3) * 2;
            float t0 = bias_a[c0] + bias_b[c0];
            float t1 = bias_a[c0 + 1] + bias_b[c0 + 1];
            float v0 = acc[im][in][0] + t0, v1 = acc[im][in][1] + t1;
            float v2 = acc[im][in][2] + t0, v3 = acc[im][in][3] + t1;
            int t  = r0 & (TT - 1), n = r0 >> 5;
            *(float2*)&Of[((size_t)t * NSEQ + n) * HH + c0] = make_float2(v0, v1);
            int t2 = (r0 + 8) & (TT - 1), n2 = (r0 + 8) >> 5;
            *(float2*)&Of[((size_t)t2 * NSEQ + n2) * HH + c0] = make_float2(v2, v3);
        }
}

// ================= 16-warp double-buffered GEMM core (recurrence) =================
struct Sm16 {
    bf16 A[2][BM][BKP2];
    bf16 B[2][BN][BKP2];
};
#define SM16_BYTES ((int)(2 * sizeof(Sm16)))

struct ChunkRegs { uint4 ra0, ra1, rl0, rl1, rb0, rb1; };

template<bool ACG>
__device__ __forceinline__ void load_chunk(
    ChunkRegs& r,
    const bf16* __restrict__ Ah, const bf16* __restrict__ Al,
    const bf16* __restrict__ Bh, const bf16* __restrict__ Bl,
    int K, int m0, int n0, int kc, int lrow, int lcol)
{
    const bf16* pA  = Ah + (size_t)(m0 + lrow) * K + kc * BK2 + lcol;
    const bf16* pAl = Al + (size_t)(m0 + lrow) * K + kc * BK2 + lcol;
    const bf16* pB  = Bh + (size_t)(n0 + lrow) * K + kc * BK2 + lcol;
    const bf16* pBl = Bl + (size_t)(n0 + lrow) * K + kc * BK2 + lcol;
    r.ra0 = ldA<ACG>(pA);
    r.ra1 = ldA<ACG>(pA + (size_t)64 * K);
    r.rl0 = ldA<ACG>(pAl);
    r.rl1 = ldA<ACG>(pAl + (size_t)64 * K);
    r.rb0 = *(const uint4*)pB;
    r.rb1 = *(const uint4*)pBl;
}

__device__ __forceinline__ void store_chunk(Sm16& s, const ChunkRegs& r, int lrow, int lcol) {
    *(uint4*)&s.A[0][lrow][lcol]      = r.ra0;
    *(uint4*)&s.A[0][lrow + 64][lcol] = r.ra1;
    *(uint4*)&s.A[1][lrow][lcol]      = r.rl0;
    *(uint4*)&s.A[1][lrow + 64][lcol] = r.rl1;
    *(uint4*)&s.B[0][lrow][lcol]      = r.rb0;
    *(uint4*)&s.B[1][lrow][lcol]      = r.rb1;
}

template<bool ACG>
__device__ __forceinline__ void accumulate16(
    Sm16* buf,
    const bf16* __restrict__ Ah, const bf16* __restrict__ Al,
    const bf16* __restrict__ Bh, const bf16* __restrict__ Bl, int K,
    int m0, int n0, float (&acc)[2][2][4])
{
    const int tid  = threadIdx.x;
    const int lane = tid & 31;
    const int wid  = tid >> 5;       // 0..15
    const int wm   = wid & 3;
    const int wn   = wid >> 2;
    const int lrow = tid >> 3;       // 0..63
    const int lcol = (tid & 7) * 8;  // 0..56

    const int a_r = wm * 32 + (lane & 15);
    const int a_c = (lane >> 4) * 8;
    const int b_r = wn * 16 + (lane & 7);
    const int b_c = ((lane & 15) >> 3) * 8;

    const int nc = K / BK2;
    ChunkRegs r;
    load_chunk<ACG>(r, Ah, Al, Bh, Bl, K, m0, n0, 0, lrow, lcol);
    store_chunk(buf[0], r, lrow, lcol);
    if (nc > 1) load_chunk<ACG>(r, Ah, Al, Bh, Bl, K, m0, n0, 1, lrow, lcol);
    __syncthreads();

    for (int kc = 0; kc < nc; kc++) {
        Sm16& sc = buf[kc & 1];
        #pragma unroll
        for (int s = 0; s < 4; s++) {
            uint32_t ah[2][4], alr[2][4], bh[2][2], bl[2][2];
            #pragma unroll
            for (int im = 0; im < 2; im++) {
                ldsm4(ah[im],  (uint32_t)__cvta_generic_to_shared(&sc.A[0][a_r + im*16][a_c + s*16]));
                ldsm4(alr[im], (uint32_t)__cvta_generic_to_shared(&sc.A[1][a_r + im*16][a_c + s*16]));
            }
            #pragma unroll
            for (int in = 0; in < 2; in++) {
                ldsm2(bh[in], (uint32_t)__cvta_generic_to_shared(&sc.B[0][b_r + in*8][b_c + s*16]));
                ldsm2(bl[in], (uint32_t)__cvta_generic_to_shared(&sc.B[1][b_r + in*8][b_c + s*16]));
            }
            #pragma unroll
            for (int im = 0; im < 2; im++)
                #pragma unroll
                for (int in = 0; in < 2; in++) {
                    mma16816(acc[im][in], ah[im],  bh[in]);
                    mma16816(acc[im][in], ah[im],  bl[in]);
                    mma16816(acc[im][in], alr[im], bh[in]);
                }
        }
        if (kc + 1 < nc) {
            store_chunk(buf[(kc + 1) & 1], r, lrow, lcol);
            if (kc + 2 < nc) load_chunk<ACG>(r, Ah, Al, Bh, Bl, K, m0, n0, kc + 2, lrow, lcol);
            __syncthreads();
        }
    }
}

// ---------------- grid barrier ----------------
__device__ __forceinline__ void grid_sync_rec() {
    __syncthreads();
    if (threadIdx.x == 0) {
        __threadfence();
        unsigned gen = *(volatile unsigned*)&g_bar_gen;
        unsigned t = atomicAdd(&g_bar_cnt, 1u);
        if (t == NCTA_REC - 1u) {
            g_bar_cnt = 0u;
            __threadfence();
            *(volatile unsigned*)&g_bar_gen = gen + 1u;
        } else {
            while (*(volatile unsigned*)&g_bar_gen == gen) { __nanosleep(32); }
        }
        __threadfence();
    }
    __syncthreads();
}

// store one epilogue fragment (hi/lo bf16 planes)
__device__ __forceinline__ void store_hfrag(
    bf16* __restrict__ Hh, bf16* __restrict__ Hl,
    int r0, int c0, float v0, float v1, float v2, float v3)
{
    bf16 a0 = __float2bfloat16(v0), a1 = __float2bfloat16(v1);
    bf16 a2 = __float2bfloat16(v2), a3 = __float2bfloat16(v3);
    __nv_bfloat162 p;
    p.x = a0; p.y = a1; *(__nv_bfloat162*)&Hh[(size_t)r0 * HH + c0] = p;
    p.x = a2; p.y = a3; *(__nv_bfloat162*)&Hh[(size_t)(r0 + 8) * HH + c0] = p;
    bf16 l0 = __float2bfloat16(v0 - __bfloat162float(a0));
    bf16 l1 = __float2bfloat16(v1 - __bfloat162float(a1));
    bf16 l2 = __float2bfloat16(v2 - __bfloat162float(a2));
    bf16 l3 = __float2bfloat16(v3 - __bfloat162float(a3));
    p.x = l0; p.y = l1; *(__nv_bfloat162*)&Hl[(size_t)r0 * HH + c0] = p;
    p.x = l2; p.y = l3; *(__nv_bfloat162*)&Hl[(size_t)(r0 + 8) * HH + c0] = p;
}

__global__ __launch_bounds__(NT2, 1) void recurrence_persistent(
    const bf16* __restrict__ Wh, const bf16* __restrict__ Wl,
    const float* __restrict__ pre0,
    const float* __restrict__ b_ih1, const float* __restrict__ b_hh1,
    bf16* __restrict__ h0h, bf16* __restrict__ h0l,
    bf16* __restrict__ h1h, bf16* __restrict__ h1l,
    float* __restrict__ h1f)
{
    extern __shared__ Sm16 smbuf[];   // 2 buffers
    const size_t PL = (size_t)NSEQ * HH;
    const int m0 = blockIdx.y * BM;
    const int n0 = blockIdx.x * BN;
    const int tid = threadIdx.x, lane = tid & 31, wid = tid >> 5;
    const int wm = wid & 3, wn = wid >> 2;

    // phase -1: h0(0) = relu(pre0[0])  (h_{-1} = 0, no GEMM)
    #pragma unroll
    for (int im = 0; im < 2; im++)
        #pragma unroll
        for (int in = 0; in < 2; in++) {
            int r0 = m0 + wm * 32 + im * 16 + (lane >> 2);
            int c0 = n0 + wn * 16 + in * 8 + (lane & 3) * 2;
            float2 q0 = *(const float2*)&pre0[(size_t)r0 * HH + c0];
            float2 q1 = *(const float2*)&pre0[(size_t)(r0 + 8) * HH + c0];
            store_hfrag(h0h, h0l, r0, c0,
                        fmaxf(q0.x, 0.f), fmaxf(q0.y, 0.f),
                        fmaxf(q1.x, 0.f), fmaxf(q1.y, 0.f));   // slot 0
        }
    grid_sync_rec();

    for (int t = 0; t < TT; t++) {
        const int s_cur = t & 1, s_nxt = s_cur ^ 1;

        // ---- layer1(t): h1_t = relu(ih1(h0_t) + hh1(h1_{t-1}) + b) ----
        float acc[2][2][4];
        #pragma unroll
        for (int i = 0; i < 2; i++)
            #pragma unroll
            for (int j = 0; j < 2; j++)
                #pragma unroll
                for (int k = 0; k < 4; k++) acc[i][j][k] = 0.f;

        accumulate16<true>(smbuf, h0h + s_cur * PL, h0l + s_cur * PL,
                           Wh + OFF_IH1, Wl + OFF_IH1, HH, m0, n0, acc);
        if (t > 0)
            accumulate16<true>(smbuf, h1h + s_nxt * PL, h1l + s_nxt * PL,
                               Wh + OFF_HH1, Wl + OFF_HH1, HH, m0, n0, acc);

        #pragma unroll
        for (int im = 0; im < 2; im++)
            #pragma unroll
            for (int in = 0; in < 2; in++) {
                int r0 = m0 + wm * 32 + im * 16 + (lane >> 2);
                int c0 = n0 + wn * 16 + in * 8 + (lane & 3) * 2;
                float t0 = b_ih1[c0] + b_hh1[c0];
                float t1 = b_ih1[c0 + 1] + b_hh1[c0 + 1];
                float v0 = fmaxf(acc[im][in][0] + t0, 0.f);
                float v1 = fmaxf(acc[im][in][1] + t1, 0.f);
                float v2 = fmaxf(acc[im][in][2] + t0, 0.f);
                float v3 = fmaxf(acc[im][in][3] + t1, 0.f);
                store_hfrag(h1h + s_cur * PL, h1l + s_cur * PL, r0, c0, v0, v1, v2, v3);
                if (t == TT - 1) {
                    *(float2*)&h1f[(size_t)r0 * HH + c0] = make_float2(v0, v1);
                    *(float2*)&h1f[(size_t)(r0 + 8) * HH + c0] = make_float2(v2, v3);
                }
            }

        // ---- layer0(t+1): h0_{t+1} = relu(pre0[t+1] + hh0(h0_t)) ----
        if (t + 1 < TT) {
            #pragma unroll
            for (int i = 0; i < 2; i++)
                #pragma unroll
                for (int j = 0; j < 2; j++)
                    #pragma unroll
                    for (int k = 0; k < 4; k++) acc[i][j][k] = 0.f;

            accumulate16<true>(smbuf, h0h + s_cur * PL, h0l + s_cur * PL,
                               Wh + OFF_HH0, Wl + OFF_HH0, HH, m0, n0, acc);

            const float* p0t = pre0 + (size_t)(t + 1) * PL;
            #pragma unroll
            for (int im = 0; im < 2; im++)
                #pragma unroll
                for (int in = 0; in < 2; in++) {
                    int r0 = m0 + wm * 32 + im * 16 + (lane >> 2);
                    int c0 = n0 + wn * 16 + in * 8 + (lane & 3) * 2;
                    float2 q0 = *(const float2*)&p0t[(size_t)r0 * HH + c0];
                    float2 q1 = *(const float2*)&p0t[(size_t)(r0 + 8) * HH + c0];
                    float v0 = fmaxf(acc[im][in][0] + q0.x, 0.f);
                    float v1 = fmaxf(acc[im][in][1] + q0.y, 0.f);
                    float v2 = fmaxf(acc[im][in][2] + q1.x, 0.f);
                    float v3 = fmaxf(acc[im][in][3] + q1.y, 0.f);
                    store_hfrag(h0h + s_nxt * PL, h0l + s_nxt * PL, r0, c0, v0, v1, v2, v3);
                }
        }

        grid_sync_rec();
    }
}

__global__ void embed_kernel(const int* __restrict__ x, const float* __restrict__ embed) {
    size_t i = (size_t)blockIdx.x * blockDim.x + threadIdx.x;
    size_t r  = i >> 6;
    int    e4 = (int)(i & 63) << 2;
    int tok = x[r];
    float4 v = *(const float4*)(embed + (size_t)tok * EE + e4);
    size_t off = r * EE + e4;
    float vv[4] = {v.x, v.y, v.z, v.w};
    bf16 h[4], l[4];
    #pragma unroll
    for (int j = 0; j < 4; j++) {
        h[j] = __float2bfloat16(vv[j]);
        l[j] = __float2bfloat16(vv[j] - __bfloat162float(h[j]));
    }
    __nv_bfloat162 h01, h23, l01, l23;
    h01.x = h[0]; h01.y = h[1]; h23.x = h[2]; h23.y = h[3];
    l01.x = l[0]; l01.y = l[1]; l23.x = l[2]; l23.y = l[3];
    uint2 uh = make_uint2(*(uint32_t*)&h01, *(uint32_t*)&h23);
    uint2 ul = make_uint2(*(uint32_t*)&l01, *(uint32_t*)&l23);
    *(uint2*)&g_Ah[off] = uh;
    *(uint2*)&g_Al[off] = ul;
}

__global__ void convert_weights(const float* __restrict__ w0, const float* __restrict__ w1,
                                const float* __restrict__ w2, const float* __restrict__ w3) {
    int i = blockIdx.x * 256 + threadIdx.x;
    if (i >= WTOT) return;
    float v;
    if      (i < OFF_HH0) v = w0[i - OFF_IH0];
    else if (i < OFF_IH1) v = w1[i - OFF_HH0];
    else if (i < OFF_HH1) v = w2[i - OFF_IH1];
    else                  v = w3[i - OFF_HH1];
    bf16 h = __float2bfloat16(v);
    g_Wh[i] = h;
    g_Wl[i] = __float2bfloat16(v - __bfloat162float(h));
}

__global__ void final_kernel(const float* __restrict__ h1, const float* __restrict__ Wp,
                             const float* __restrict__ bp, float* __restrict__ out) {
    __shared__ float wc[1024];
    __shared__ float red[256];
    __shared__ float ctermS;
    int b = blockIdx.x, tid = threadIdx.x;
    const float* Hb = h1 + (size_t)b * 256 * HH;
    float s0 = 0.f, s1 = 0.f;
    for (int cell = 0; cell < 256; cell++) {
        const float* row = Hb + (size_t)cell * HH;
        s0 += row[tid];
        s1 += row[tid + 256];
    }
    wc[tid]       = Wp[tid]       - Wp[HH + tid];
    wc[tid + 256] = Wp[tid + 256] - Wp[HH + tid + 256];
    red[tid] = s0 * Wp[HH + tid] + s1 * Wp[HH + tid + 256];
    __syncthreads();
    for (int s = 128; s > 0; s >>= 1) {
        if (tid < s) red[tid] += red[tid + s];
        __syncthreads();
    }
    if (tid == 0) ctermS = red[0] + bp[0];
    __syncthreads();
    int warp = tid >> 5, lane = tid & 31;
    for (int cell = warp; cell < 256; cell += 8) {
        const float* row = Hb + (size_t)cell * HH;
        float a = 0.f;
        for (int c = lane; c < HH; c += 32) a += row[c] * wc[c];
        #pragma unroll
        for (int o = 16; o; o >>= 1) a += __shfl_xor_sync(0xffffffffu, a, o);
        if (lane == 0) out[(size_t)b * 256 + cell] = a + ctermS;
    }
}

extern "C" void kernel_launch(void* const* d_in, const int* in_sizes, int n_in,
                              void* d_out, int out_size) {
    (void)in_sizes; (void)n_in; (void)out_size;
    const int*   x      = (const int*)  d_in[0];
    const float* embedp = (const float*)d_in[1];
    const float* W_ih0  = (const float*)d_in[2];
    const float* W_hh0  = (const float*)d_in[3];
    const float* b_ih0  = (const float*)d_in[4];
    const float* b_hh0  = (const float*)d_in[5];
    const float* W_ih1  = (const float*)d_in[6];
    const float* W_hh1  = (const float*)d_in[7];
    const float* b_ih1  = (const float*)d_in[8];
    const float* b_hh1  = (const float*)d_in[9];
    const float* W_pred = (const float*)d_in[10];
    const float* b_pred = (const float*)d_in[11];
    float* out = (float*)d_out;

    bf16 *Ah, *Al, *Wh, *Wl, *h0h, *h0l, *h1h, *h1l;
    float *pre0, *h1f;
    cudaGetSymbolAddress((void**)&Ah,  g_Ah);
    cudaGetSymbolAddress((void**)&Al,  g_Al);
    cudaGetSymbolAddress((void**)&Wh,  g_Wh);
    cudaGetSymbolAddress((void**)&Wl,  g_Wl);
    cudaGetSymbolAddress((void**)&h0h, g_h0h);
    cudaGetSymbolAddress((void**)&h0l, g_h0l);
    cudaGetSymbolAddress((void**)&h1h, g_h1h);
    cudaGetSymbolAddress((void**)&h1l, g_h1l);
    cudaGetSymbolAddress((void**)&pre0, g_pre0);
    cudaGetSymbolAddress((void**)&h1f,  g_h1f);

    cudaFuncSetAttribute(recurrence_persistent,
                         cudaFuncAttributeMaxDynamicSharedMemorySize, SM16_BYTES);

    convert_weights<<<(WTOT + 255) / 256, 256>>>(W_ih0, W_hh0, W_ih1, W_hh1);
    embed_kernel<<<(MROWS * EE / 4 + 255) / 256, 256>>>(x, embedp);

    gemm3p<<<dim3(HH / BN, MROWS / BM), NT>>>(
        Ah, Al, Wh + OFF_IH0, Wl + OFF_IH0, EE, b_ih0, b_hh0, pre0);

    recurrence_persistent<<<dim3(HH / BN, NSEQ / BM), NT2, SM16_BYTES>>>(
        Wh, Wl, pre0, b_ih1, b_hh1, h0h, h0l, h1h, h1l, h1f);

    final_kernel<<<8, 256>>>(h1f, W_pred, b_pred, out);
}